// round 9
// baseline (speedup 1.0000x reference)
#include <cuda_runtime.h>
#include <math.h>

#define T      2048
#define DM     2048
#define NH     16
#define NKV    4
#define HD     128
#define NEXP   16
#define TK     8
#define IR     1024
#define ISH    4096

// ---------------- scratch (device globals; no allocation allowed) ----------------
__device__ float g_xn   [T*DM];
__device__ float g_q    [T*NH*HD];
__device__ float g_k    [T*NKV*HD];
__device__ float g_v    [T*NKV*HD];
__device__ float g_attn [T*NH*HD];
__device__ float g_hid  [T*DM];
__device__ float g_x2n  [T*DM];
__device__ float g_G    [T*ISH];
__device__ float g_U    [T*ISH];
__device__ float g_H    [T*ISH];
__device__ float g_sh   [T*DM];
__device__ int   g_cnt  [NEXP];
__device__ int   g_tok  [NEXP*T];
__device__ int   g_slot [T*TK];
__device__ int   g_eid  [T*TK];
__device__ float g_wt   [T*TK];
__device__ float g_eG   [NEXP*T*IR];
__device__ float g_eU   [NEXP*T*IR];
__device__ float g_eH   [NEXP*T*IR];
__device__ float g_eO   [NEXP*T*DM];

// ---------------- RMSNorm over DM per token ----------------
__global__ void k_rms(const float* __restrict__ x, const float* __restrict__ w,
                      float* __restrict__ y)
{
    int t = blockIdx.x;
    const float* xr = x + (long)t * DM;
    float v[8];
    float s = 0.f;
#pragma unroll
    for (int i = 0; i < 8; ++i) {
        v[i] = xr[threadIdx.x + i * 256];
        s = fmaf(v[i], v[i], s);
    }
#pragma unroll
    for (int o = 16; o > 0; o >>= 1) s += __shfl_xor_sync(0xffffffffu, s, o);
    __shared__ float red[8];
    __shared__ float rstd;
    if ((threadIdx.x & 31) == 0) red[threadIdx.x >> 5] = s;
    __syncthreads();
    if (threadIdx.x == 0) {
        float tot = 0.f;
#pragma unroll
        for (int i = 0; i < 8; ++i) tot += red[i];
        rstd = rsqrtf(tot / (float)DM + 1e-6f);
    }
    __syncthreads();
    float r = rstd;
#pragma unroll
    for (int i = 0; i < 8; ++i) {
        int d = threadIdx.x + i * 256;
        y[(long)t * DM + d] = w[d] * (v[i] * r);
    }
}

// ---------------- RoPE + per-head RMSNorm (q and k), 128 threads = head_dim ----------------
__global__ void k_rope(float* __restrict__ q, float* __restrict__ k,
                       const float* __restrict__ cosT, const float* __restrict__ sinT,
                       const float* __restrict__ qn, const float* __restrict__ kn)
{
    int t = blockIdx.x;
    int h = blockIdx.y;              // 0..15 -> q heads, 16..19 -> k heads
    int d = threadIdx.x;             // 0..127
    float* p;
    const float* nw;
    if (h < NH) { p = q + (long)t * (NH*HD) + h * HD; nw = qn; }
    else        { p = k + (long)t * (NKV*HD) + (h - NH) * HD; nw = kn; }
    float x = p[d];
    float o = (d < 64) ? -p[d + 64] : p[d - 64];
    float c = cosT[t * HD + d];
    float s = sinT[t * HD + d];
    float r = fmaf(x, c, o * s);
    float sq = r * r;
#pragma unroll
    for (int off = 16; off > 0; off >>= 1) sq += __shfl_xor_sync(0xffffffffu, sq, off);
    __shared__ float red[4];
    __shared__ float rstd;
    if ((d & 31) == 0) red[d >> 5] = sq;
    __syncthreads();
    if (d == 0) rstd = rsqrtf((red[0] + red[1] + red[2] + red[3]) / (float)HD + 1e-6f);
    __syncthreads();
    p[d] = nw[d] * (r * rstd);
}

// ---------------- SGEMM: C[M,N] = A[M,K] * B[N,K]^T (+Add), 128x128x8, 256 thr ----------------
// Expert modes: cnt!=null -> M = cnt[blockIdx.z]; tok!=null -> gather A rows from Xg by index.
__global__ __launch_bounds__(256, 2)
void k_gemm(const float* __restrict__ A, long aStrE,
            const float* __restrict__ B, long bStrE,
            float* __restrict__ C, long cStrE,
            const float* __restrict__ Add,
            int M, int N, int K,
            const int* __restrict__ cnt,
            const int* __restrict__ tok,
            const float* __restrict__ Xg)
{
    int e  = blockIdx.z;
    int Me = cnt ? cnt[e] : M;
    int bm = blockIdx.y * 128;
    if (bm >= Me) return;
    int bn = blockIdx.x * 128;
    const float* Bp = B + (long)e * bStrE;
    float*       Cp = C + (long)e * cStrE;

    __shared__ float As[8][128];
    __shared__ float Bs[8][128];

    int tid  = threadIdx.x;
    int lrow = tid >> 1;
    int lcol = (tid & 1) * 4;

    const float* Arow;
    {
        int gr = bm + lrow;
        if (tok) {
            const int* tp = tok + e * T;
            int tt = (gr < Me) ? tp[gr] : tp[0];
            Arow = Xg + (long)tt * K;
        } else {
            int r = (gr < Me) ? gr : 0;
            Arow = A + (long)e * aStrE + (long)r * K;
        }
    }
    const float* Brow = Bp + (long)(bn + lrow) * K;

    int ty = tid >> 4;
    int tx = tid & 15;

    float acc[8][8];
#pragma unroll
    for (int i = 0; i < 8; ++i)
#pragma unroll
        for (int j = 0; j < 8; ++j) acc[i][j] = 0.f;

    float4 a4 = *(const float4*)(Arow + lcol);
    float4 b4 = *(const float4*)(Brow + lcol);

    for (int k0 = 0; k0 < K; k0 += 8) {
        As[lcol+0][lrow] = a4.x; As[lcol+1][lrow] = a4.y;
        As[lcol+2][lrow] = a4.z; As[lcol+3][lrow] = a4.w;
        Bs[lcol+0][lrow] = b4.x; Bs[lcol+1][lrow] = b4.y;
        Bs[lcol+2][lrow] = b4.z; Bs[lcol+3][lrow] = b4.w;
        __syncthreads();
        if (k0 + 8 < K) {
            a4 = *(const float4*)(Arow + k0 + 8 + lcol);
            b4 = *(const float4*)(Brow + k0 + 8 + lcol);
        }
#pragma unroll
        for (int kk = 0; kk < 8; ++kk) {
            float ar[8], br[8];
            *(float4*)&ar[0] = *(const float4*)&As[kk][ty*8];
            *(float4*)&ar[4] = *(const float4*)&As[kk][ty*8+4];
            *(float4*)&br[0] = *(const float4*)&Bs[kk][tx*8];
            *(float4*)&br[4] = *(const float4*)&Bs[kk][tx*8+4];
#pragma unroll
            for (int i = 0; i < 8; ++i)
#pragma unroll
                for (int j = 0; j < 8; ++j)
                    acc[i][j] = fmaf(ar[i], br[j], acc[i][j]);
        }
        __syncthreads();
    }

#pragma unroll
    for (int i = 0; i < 8; ++i) {
        int gr = bm + ty * 8 + i;
        if (gr < Me) {
            long off = (long)gr * N + bn + tx * 8;
            float4 c0 = make_float4(acc[i][0], acc[i][1], acc[i][2], acc[i][3]);
            float4 c1 = make_float4(acc[i][4], acc[i][5], acc[i][6], acc[i][7]);
            if (Add) {
                float4 d0 = *(const float4*)(Add + off);
                float4 d1 = *(const float4*)(Add + off + 4);
                c0.x += d0.x; c0.y += d0.y; c0.z += d0.z; c0.w += d0.w;
                c1.x += d1.x; c1.y += d1.y; c1.z += d1.z; c1.w += d1.w;
            }
            *(float4*)(Cp + off)     = c0;
            *(float4*)(Cp + off + 4) = c1;
        }
    }
}

// ---------------- causal GQA attention, fp32 flash-style; 64 q rows/block ----------------
__global__ __launch_bounds__(256)
void k_attn(const float* __restrict__ Q, const float* __restrict__ K,
            const float* __restrict__ V, float* __restrict__ O)
{
    extern __shared__ float sm[];
    float* Qs = sm;                  // 64*128
    float* Ks = Qs + 64 * HD;        // 64*128
    float* Vs = Ks + 64 * HD;        // 64*128
    float* Ss = Vs + 64 * HD;        // 64*64

    int h   = blockIdx.y;
    int qb  = blockIdx.x * 64;
    int kvh = h >> 2;
    int tid = threadIdx.x;

    for (int f = tid; f < 64 * 32; f += 256) {
        int r = f >> 5, c = (f & 31) << 2;
        *(float4*)&Qs[r * HD + c] =
            *(const float4*)&Q[(long)(qb + r) * (NH*HD) + h * HD + c];
    }

    int r  = tid >> 2;               // owned output row 0..63
    int c0 = (tid & 3) * 32;         // owned 32-col slab
    int ty = tid >> 4, tx = tid & 15;

    float acc[32];
#pragma unroll
    for (int i = 0; i < 32; ++i) acc[i] = 0.f;
    float mx = -INFINITY, l = 0.f;
    const float scale = 0.0883883476483184f; // 128^-0.5

    int nkt = (qb >> 6) + 1;
    for (int kt = 0; kt < nkt; ++kt) {
        int kb = kt << 6;
        __syncthreads();
        for (int f = tid; f < 64 * 32; f += 256) {
            int rr = f >> 5, cc = (f & 31) << 2;
            *(float4*)&Ks[rr * HD + cc] =
                *(const float4*)&K[(long)(kb + rr) * (NKV*HD) + kvh * HD + cc];
            *(float4*)&Vs[rr * HD + cc] =
                *(const float4*)&V[(long)(kb + rr) * (NKV*HD) + kvh * HD + cc];
        }
        __syncthreads();

        // S = Q K^T  (4x4 per thread)
        float s4[4][4];
#pragma unroll
        for (int i = 0; i < 4; ++i)
#pragma unroll
            for (int j = 0; j < 4; ++j) s4[i][j] = 0.f;
        for (int d = 0; d < HD; d += 4) {
            float4 qv[4], kv[4];
#pragma unroll
            for (int i = 0; i < 4; ++i) qv[i] = *(const float4*)&Qs[(ty*4 + i) * HD + d];
#pragma unroll
            for (int j = 0; j < 4; ++j) kv[j] = *(const float4*)&Ks[(tx*4 + j) * HD + d];
#pragma unroll
            for (int i = 0; i < 4; ++i)
#pragma unroll
                for (int j = 0; j < 4; ++j) {
                    s4[i][j] = fmaf(qv[i].x, kv[j].x, s4[i][j]);
                    s4[i][j] = fmaf(qv[i].y, kv[j].y, s4[i][j]);
                    s4[i][j] = fmaf(qv[i].z, kv[j].z, s4[i][j]);
                    s4[i][j] = fmaf(qv[i].w, kv[j].w, s4[i][j]);
                }
        }
#pragma unroll
        for (int i = 0; i < 4; ++i)
#pragma unroll
            for (int j = 0; j < 4; ++j) {
                int qg = qb + ty*4 + i, kg = kb + tx*4 + j;
                Ss[(ty*4 + i) * 64 + tx*4 + j] = (kg <= qg) ? s4[i][j] * scale : -1e30f;
            }
        __syncthreads();

        // streaming softmax (4 lanes per row)
        int jc = (tid & 3) * 16;
        float tmax = -1e30f;
#pragma unroll
        for (int j = 0; j < 16; ++j) tmax = fmaxf(tmax, Ss[r * 64 + jc + j]);
        tmax = fmaxf(tmax, __shfl_xor_sync(0xffffffffu, tmax, 1));
        tmax = fmaxf(tmax, __shfl_xor_sync(0xffffffffu, tmax, 2));
        float mn = fmaxf(mx, tmax);
        float psum = 0.f;
#pragma unroll
        for (int j = 0; j < 16; ++j) {
            float p = expf(Ss[r * 64 + jc + j] - mn);
            Ss[r * 64 + jc + j] = p;
            psum += p;
        }
        psum += __shfl_xor_sync(0xffffffffu, psum, 1);
        psum += __shfl_xor_sync(0xffffffffu, psum, 2);
        float corr = expf(mx - mn);
        l = l * corr + psum;
        mx = mn;
#pragma unroll
        for (int i = 0; i < 32; ++i) acc[i] *= corr;
        __syncwarp();

        // O += P V
        for (int j = 0; j < 64; ++j) {
            float p = Ss[r * 64 + j];
            const float4* v4 = (const float4*)&Vs[j * HD + c0];
#pragma unroll
            for (int i = 0; i < 8; ++i) {
                float4 vv = v4[i];
                acc[i*4+0] = fmaf(p, vv.x, acc[i*4+0]);
                acc[i*4+1] = fmaf(p, vv.y, acc[i*4+1]);
                acc[i*4+2] = fmaf(p, vv.z, acc[i*4+2]);
                acc[i*4+3] = fmaf(p, vv.w, acc[i*4+3]);
            }
        }
    }
    float inv = 1.f / l;
#pragma unroll
    for (int i = 0; i < 8; ++i) {
        float4 o4 = make_float4(acc[i*4]*inv, acc[i*4+1]*inv, acc[i*4+2]*inv, acc[i*4+3]*inv);
        *(float4*)&O[(long)(qb + r) * (NH*HD) + h * HD + c0 + i*4] = o4;
    }
}

// ---------------- elementwise silu(G)*U ----------------
__global__ void k_silu(const float* __restrict__ G, const float* __restrict__ U,
                       float* __restrict__ H, int n)
{
    int stride = gridDim.x * 256;
    for (int i = blockIdx.x * 256 + threadIdx.x; i < n; i += stride) {
        float g = G[i];
        H[i] = (g / (1.f + expf(-g))) * U[i];
    }
}

__global__ void k_silu_exp()
{
    int e = blockIdx.y;
    int n = g_cnt[e] * IR;
    int base = e * T * IR;
    int stride = gridDim.x * 256;
    for (int i = blockIdx.x * 256 + threadIdx.x; i < n; i += stride) {
        float g = g_eG[base + i];
        g_eH[base + i] = (g / (1.f + expf(-g))) * g_eU[base + i];
    }
}

// ---------------- router: logits, softmax, top-8, slot assignment ----------------
__global__ void k_zero() { if (threadIdx.x < NEXP) g_cnt[threadIdx.x] = 0; }

__global__ void k_route(const float* __restrict__ x, const float* __restrict__ gw)
{
    int t = blockIdx.x;
    __shared__ float xs[DM];
    __shared__ float lg[NEXP];
    for (int d = threadIdx.x; d < DM; d += 256) xs[d] = x[(long)t * DM + d];
    __syncthreads();
    int e = threadIdx.x >> 4;
    int part = threadIdx.x & 15;
    float s = 0.f;
    const float* gr = gw + e * DM;
    for (int d = part; d < DM; d += 16) s = fmaf(xs[d], gr[d], s);
    s += __shfl_xor_sync(0xffffffffu, s, 1);
    s += __shfl_xor_sync(0xffffffffu, s, 2);
    s += __shfl_xor_sync(0xffffffffu, s, 4);
    s += __shfl_xor_sync(0xffffffffu, s, 8);
    if (part == 0) lg[e] = s;
    __syncthreads();
    if (threadIdx.x == 0) {
        float m = lg[0];
#pragma unroll
        for (int i = 1; i < NEXP; ++i) m = fmaxf(m, lg[i]);
        float p[NEXP]; float tot = 0.f;
#pragma unroll
        for (int i = 0; i < NEXP; ++i) { p[i] = expf(lg[i] - m); tot += p[i]; }
#pragma unroll
        for (int i = 0; i < NEXP; ++i) p[i] /= tot;
        bool used[NEXP];
#pragma unroll
        for (int i = 0; i < NEXP; ++i) used[i] = false;
        int sel[TK]; float sw[TK]; float wsum = 0.f;
        for (int j = 0; j < TK; ++j) {
            int b = 0; float bv = -1.f;
#pragma unroll
            for (int i = 0; i < NEXP; ++i)
                if (!used[i] && p[i] > bv) { bv = p[i]; b = i; }
            used[b] = true; sel[j] = b; sw[j] = bv; wsum += bv;
        }
        for (int j = 0; j < TK; ++j) {
            int ee = sel[j];
            int slot = atomicAdd(&g_cnt[ee], 1);
            g_tok[ee * T + slot] = t;
            g_eid[t * TK + j]  = ee;
            g_slot[t * TK + j] = slot;
            g_wt[t * TK + j]   = sw[j] / wsum;
        }
    }
}

// ---------------- final combine: residual2 + shared + sum_j w_j * expert_out ----------------
__global__ void k_combine(const float* __restrict__ hid, const float* __restrict__ sh,
                          float* __restrict__ out)
{
    int t = blockIdx.x;
    long bo[TK]; float w[TK];
#pragma unroll
    for (int j = 0; j < TK; ++j) {
        int e = g_eid[t * TK + j];
        int s = g_slot[t * TK + j];
        w[j] = g_wt[t * TK + j];
        bo[j] = ((long)e * T + s) * (long)DM;
    }
    for (int d = threadIdx.x; d < DM; d += 256) {
        float v = hid[(long)t * DM + d] + sh[(long)t * DM + d];
#pragma unroll
        for (int j = 0; j < TK; ++j) v = fmaf(w[j], g_eO[bo[j] + d], v);
        out[(long)t * DM + d] = v;
    }
}

// ---------------- host ----------------
extern "C" void kernel_launch(void* const* d_in, const int* in_sizes, int n_in,
                              void* d_out, int out_size)
{
    (void)in_sizes; (void)n_in; (void)out_size;
    const float* hs   = (const float*)d_in[0];
    /* d_in[1] position_ids == arange(2048): indexed implicitly by row */
    const float* cosT = (const float*)d_in[2];
    const float* sinT = (const float*)d_in[3];
    const float* ln1  = (const float*)d_in[4];
    const float* ln2  = (const float*)d_in[5];
    const float* wq   = (const float*)d_in[6];
    const float* wk   = (const float*)d_in[7];
    const float* wv   = (const float*)d_in[8];
    const float* wo   = (const float*)d_in[9];
    const float* qn   = (const float*)d_in[10];
    const float* kn   = (const float*)d_in[11];
    const float* gw   = (const float*)d_in[12];
    const float* sg   = (const float*)d_in[13];
    const float* su   = (const float*)d_in[14];
    const float* sd   = (const float*)d_in[15];
    const float* eg   = (const float*)d_in[16];
    const float* eu   = (const float*)d_in[17];
    const float* ed   = (const float*)d_in[18];
    float* out = (float*)d_out;

    float *p_xn, *p_q, *p_k, *p_v, *p_attn, *p_hid, *p_x2n;
    float *p_G, *p_U, *p_H, *p_sh, *p_eG, *p_eU, *p_eH, *p_eO;
    int *p_cnt, *p_tok;
    cudaGetSymbolAddress((void**)&p_xn,   g_xn);
    cudaGetSymbolAddress((void**)&p_q,    g_q);
    cudaGetSymbolAddress((void**)&p_k,    g_k);
    cudaGetSymbolAddress((void**)&p_v,    g_v);
    cudaGetSymbolAddress((void**)&p_attn, g_attn);
    cudaGetSymbolAddress((void**)&p_hid,  g_hid);
    cudaGetSymbolAddress((void**)&p_x2n,  g_x2n);
    cudaGetSymbolAddress((void**)&p_G,    g_G);
    cudaGetSymbolAddress((void**)&p_U,    g_U);
    cudaGetSymbolAddress((void**)&p_H,    g_H);
    cudaGetSymbolAddress((void**)&p_sh,   g_sh);
    cudaGetSymbolAddress((void**)&p_eG,   g_eG);
    cudaGetSymbolAddress((void**)&p_eU,   g_eU);
    cudaGetSymbolAddress((void**)&p_eH,   g_eH);
    cudaGetSymbolAddress((void**)&p_eO,   g_eO);
    cudaGetSymbolAddress((void**)&p_cnt,  g_cnt);
    cudaGetSymbolAddress((void**)&p_tok,  g_tok);

    // 1) pre-attention RMSNorm
    k_rms<<<T, 256>>>(hs, ln1, p_xn);

    // 2) QKV projections
    k_gemm<<<dim3(16, 16, 1), 256>>>(p_xn, 0, wq, 0, p_q, 0, nullptr,
                                     T, NH*HD, DM, nullptr, nullptr, nullptr);
    k_gemm<<<dim3(4, 16, 1), 256>>>(p_xn, 0, wk, 0, p_k, 0, nullptr,
                                    T, NKV*HD, DM, nullptr, nullptr, nullptr);
    k_gemm<<<dim3(4, 16, 1), 256>>>(p_xn, 0, wv, 0, p_v, 0, nullptr,
                                    T, NKV*HD, DM, nullptr, nullptr, nullptr);

    // 3) RoPE + QK-RMSNorm
    k_rope<<<dim3(T, NH + NKV), 128>>>(p_q, p_k, cosT, sinT, qn, kn);

    // 4) causal GQA attention
    cudaFuncSetAttribute(k_attn, cudaFuncAttributeMaxDynamicSharedMemorySize, 114688);
    k_attn<<<dim3(T / 64, NH), 256, 114688>>>(p_q, p_k, p_v, p_attn);

    // 5) output projection + residual
    k_gemm<<<dim3(16, 16, 1), 256>>>(p_attn, 0, wo, 0, p_hid, 0, hs,
                                     T, DM, NH*HD, nullptr, nullptr, nullptr);

    // 6) post-attention RMSNorm
    k_rms<<<T, 256>>>(p_hid, ln2, p_x2n);

    // 7) shared-expert MLP
    k_gemm<<<dim3(32, 16, 1), 256>>>(p_x2n, 0, sg, 0, p_G, 0, nullptr,
                                     T, ISH, DM, nullptr, nullptr, nullptr);
    k_gemm<<<dim3(32, 16, 1), 256>>>(p_x2n, 0, su, 0, p_U, 0, nullptr,
                                     T, ISH, DM, nullptr, nullptr, nullptr);
    k_silu<<<4096, 256>>>(p_G, p_U, p_H, T * ISH);
    k_gemm<<<dim3(16, 16, 1), 256>>>(p_H, 0, sd, 0, p_sh, 0, nullptr,
                                     T, DM, ISH, nullptr, nullptr, nullptr);

    // 8) routing
    k_zero<<<1, 32>>>();
    k_route<<<T, 256>>>(p_x2n, gw);

    // 9) routed experts: gate/up (gathered rows), silu, down
    k_gemm<<<dim3(8, 16, NEXP), 256>>>(nullptr, 0, eg, (long)IR * DM,
                                       p_eG, (long)T * IR, nullptr,
                                       0, IR, DM, p_cnt, p_tok, p_x2n);
    k_gemm<<<dim3(8, 16, NEXP), 256>>>(nullptr, 0, eu, (long)IR * DM,
                                       p_eU, (long)T * IR, nullptr,
                                       0, IR, DM, p_cnt, p_tok, p_x2n);
    k_silu_exp<<<dim3(128, NEXP), 256>>>();
    k_gemm<<<dim3(16, 16, NEXP), 256>>>(p_eH, (long)T * IR, ed, (long)DM * IR,
                                        p_eO, (long)T * DM, nullptr,
                                        0, DM, IR, p_cnt, nullptr, nullptr);

    // 10) combine
    k_combine<<<T, 256>>>(p_hid, p_sh, out);
}

// round 11
// speedup vs baseline: 1.4438x; 1.4438x over previous
#include <cuda_runtime.h>
#include <cuda_bf16.h>
#include <math.h>
#include <stdint.h>

#define T      2048
#define DM     2048
#define NH     16
#define NKV    4
#define HD     128
#define NEXP   16
#define TK     8
#define IR     1024
#define ISH    4096

// ---------------- scratch (device globals; no allocation allowed) ----------------
__device__ float g_xn   [T*DM];
__device__ float g_q    [T*NH*HD];
__device__ float g_k    [T*NKV*HD];
__device__ float g_v    [T*NKV*HD];
__device__ float g_attn [T*NH*HD];
__device__ float g_hid  [T*DM];
__device__ float g_x2n  [T*DM];
__device__ float g_G    [T*ISH];
__device__ float g_U    [T*ISH];
__device__ float g_H    [T*ISH];
__device__ float g_sh   [T*DM];
__device__ int   g_cnt  [NEXP];
__device__ int   g_tok  [NEXP*T];
__device__ int   g_slot [T*TK];
__device__ int   g_eid  [T*TK];
__device__ float g_wt   [T*TK];
__device__ float g_eG   [NEXP*T*IR];
__device__ float g_eU   [NEXP*T*IR];
__device__ float g_eH   [NEXP*T*IR];
__device__ float g_eO   [NEXP*T*DM];

// pack two floats -> bf16x2 hi word + bf16x2 lo (residual) word
__device__ __forceinline__ void split2(float x, float y, uint32_t& hi, uint32_t& lo) {
    __nv_bfloat16 hx = __float2bfloat16(x);
    __nv_bfloat16 hy = __float2bfloat16(y);
    float rx = x - __bfloat162float(hx);
    float ry = y - __bfloat162float(hy);
    __nv_bfloat16 lx = __float2bfloat16(rx);
    __nv_bfloat16 ly = __float2bfloat16(ry);
    __nv_bfloat162 h; h.x = hx; h.y = hy;
    __nv_bfloat162 l; l.x = lx; l.y = ly;
    hi = *reinterpret_cast<uint32_t*>(&h);
    lo = *reinterpret_cast<uint32_t*>(&l);
}

__device__ __forceinline__ void mma16816(float* d, const uint32_t* a, const uint32_t* b) {
    asm volatile("mma.sync.aligned.m16n8k16.row.col.f32.bf16.bf16.f32 "
        "{%0,%1,%2,%3}, {%4,%5,%6,%7}, {%8,%9}, {%0,%1,%2,%3};"
        : "+f"(d[0]), "+f"(d[1]), "+f"(d[2]), "+f"(d[3])
        : "r"(a[0]), "r"(a[1]), "r"(a[2]), "r"(a[3]), "r"(b[0]), "r"(b[1]));
}

// ---------------- RMSNorm over DM per token ----------------
__global__ void k_rms(const float* __restrict__ x, const float* __restrict__ w,
                      float* __restrict__ y)
{
    int t = blockIdx.x;
    const float* xr = x + (long)t * DM;
    float v[8];
    float s = 0.f;
#pragma unroll
    for (int i = 0; i < 8; ++i) {
        v[i] = xr[threadIdx.x + i * 256];
        s = fmaf(v[i], v[i], s);
    }
#pragma unroll
    for (int o = 16; o > 0; o >>= 1) s += __shfl_xor_sync(0xffffffffu, s, o);
    __shared__ float red[8];
    __shared__ float rstd;
    if ((threadIdx.x & 31) == 0) red[threadIdx.x >> 5] = s;
    __syncthreads();
    if (threadIdx.x == 0) {
        float tot = 0.f;
#pragma unroll
        for (int i = 0; i < 8; ++i) tot += red[i];
        rstd = rsqrtf(tot / (float)DM + 1e-6f);
    }
    __syncthreads();
    float r = rstd;
#pragma unroll
    for (int i = 0; i < 8; ++i) {
        int d = threadIdx.x + i * 256;
        y[(long)t * DM + d] = w[d] * (v[i] * r);
    }
}

// ---------------- RoPE + per-head RMSNorm (q and k) ----------------
__global__ void k_rope(float* __restrict__ q, float* __restrict__ k,
                       const float* __restrict__ cosT, const float* __restrict__ sinT,
                       const float* __restrict__ qn, const float* __restrict__ kn)
{
    int t = blockIdx.x;
    int h = blockIdx.y;
    int d = threadIdx.x;
    float* p;
    const float* nw;
    if (h < NH) { p = q + (long)t * (NH*HD) + h * HD; nw = qn; }
    else        { p = k + (long)t * (NKV*HD) + (h - NH) * HD; nw = kn; }
    float x = p[d];
    float o = (d < 64) ? -p[d + 64] : p[d - 64];
    float c = cosT[t * HD + d];
    float s = sinT[t * HD + d];
    float r = fmaf(x, c, o * s);
    float sq = r * r;
#pragma unroll
    for (int off = 16; off > 0; off >>= 1) sq += __shfl_xor_sync(0xffffffffu, sq, off);
    __shared__ float red[4];
    __shared__ float rstd;
    if ((d & 31) == 0) red[d >> 5] = sq;
    __syncthreads();
    if (d == 0) rstd = rsqrtf((red[0] + red[1] + red[2] + red[3]) / (float)HD + 1e-6f);
    __syncthreads();
    p[d] = nw[d] * (r * rstd);
}

// ================= HMMA GEMM: C[M,N] = A[M,K]*B[N,K]^T (+Add) =================
// bf16 hi/lo split in SMEM, 3 products (hh + hl + lh), fp32 accumulators.
// Tile 128x128, BK=32. 8 warps, each 64x32. cnt/tok = expert count / gather.
__global__ __launch_bounds__(256, 2)
void k_gemm_mma(const float* __restrict__ A, long aStrE,
                const float* __restrict__ B, long bStrE,
                float* __restrict__ C, long cStrE,
                const float* __restrict__ Add,
                int M, int N, int K,
                const int* __restrict__ cnt,
                const int* __restrict__ tok,
                const float* __restrict__ Xg)
{
    int e  = blockIdx.z;
    int Me = cnt ? cnt[e] : M;
    int bm = blockIdx.y * 128;
    if (bm >= Me) return;
    int bn = blockIdx.x * 128;
    const float* Bp = B + (long)e * bStrE;
    float*       Cp = C + (long)e * cStrE;

    __shared__ const float* s_arow[128];
    __shared__ __align__(16) __nv_bfloat16 sAh[128][36];
    __shared__ __align__(16) __nv_bfloat16 sAl[128][36];
    __shared__ __align__(16) __nv_bfloat16 sBh[128][36];
    __shared__ __align__(16) __nv_bfloat16 sBl[128][36];

    int tid  = threadIdx.x;
    int wid  = tid >> 5;
    int lane = tid & 31;

    if (tid < 128) {
        int gr = bm + tid;
        const float* p;
        if (tok) {
            const int* tp = tok + e * T;
            int tt = (gr < Me) ? tp[gr] : tp[0];
            p = Xg + (long)tt * K;
        } else {
            int r = (gr < Me) ? gr : 0;
            p = A + (long)e * aStrE + (long)r * K;
        }
        s_arow[tid] = p;
    }
    __syncthreads();

    int lrow = tid >> 1;
    int lcol = (tid & 1) * 16;
    const float* ap = s_arow[lrow];
    const float* bp = Bp + (long)(bn + lrow) * K;

    int wm  = (wid >> 2) * 64;
    int wn  = (wid & 3) * 32;
    int gid = lane >> 2;
    int tig = lane & 3;

    float acc[4][4][4];
#pragma unroll
    for (int i = 0; i < 4; ++i)
#pragma unroll
        for (int j = 0; j < 4; ++j)
#pragma unroll
            for (int q = 0; q < 4; ++q) acc[i][j][q] = 0.f;

    int nkc = K >> 5;
    for (int kc = 0; kc < nkc; ++kc) {
        int ko = (kc << 5) + lcol;
#pragma unroll
        for (int i = 0; i < 4; ++i) {
            float4 va = *(const float4*)(ap + ko + i * 4);
            float4 vb = *(const float4*)(bp + ko + i * 4);
            uint32_t h0, l0, h1, l1;
            split2(va.x, va.y, h0, l0);
            split2(va.z, va.w, h1, l1);
            *(uint32_t*)&sAh[lrow][lcol + i*4]     = h0;
            *(uint32_t*)&sAh[lrow][lcol + i*4 + 2] = h1;
            *(uint32_t*)&sAl[lrow][lcol + i*4]     = l0;
            *(uint32_t*)&sAl[lrow][lcol + i*4 + 2] = l1;
            split2(vb.x, vb.y, h0, l0);
            split2(vb.z, vb.w, h1, l1);
            *(uint32_t*)&sBh[lrow][lcol + i*4]     = h0;
            *(uint32_t*)&sBh[lrow][lcol + i*4 + 2] = h1;
            *(uint32_t*)&sBl[lrow][lcol + i*4]     = l0;
            *(uint32_t*)&sBl[lrow][lcol + i*4 + 2] = l1;
        }
        __syncthreads();

#pragma unroll
        for (int ks = 0; ks < 2; ++ks) {
            int kb = ks * 16 + tig * 2;
            uint32_t af[4][4], bh[4][2], bl[4][2];
            // A_hi + B_hi fragments
#pragma unroll
            for (int mt = 0; mt < 4; ++mt) {
                int r0 = wm + mt * 16 + gid;
                af[mt][0] = *(const uint32_t*)&sAh[r0][kb];
                af[mt][1] = *(const uint32_t*)&sAh[r0 + 8][kb];
                af[mt][2] = *(const uint32_t*)&sAh[r0][kb + 8];
                af[mt][3] = *(const uint32_t*)&sAh[r0 + 8][kb + 8];
            }
#pragma unroll
            for (int nt = 0; nt < 4; ++nt) {
                int rn = wn + nt * 8 + gid;
                bh[nt][0] = *(const uint32_t*)&sBh[rn][kb];
                bh[nt][1] = *(const uint32_t*)&sBh[rn][kb + 8];
                bl[nt][0] = *(const uint32_t*)&sBl[rn][kb];
                bl[nt][1] = *(const uint32_t*)&sBl[rn][kb + 8];
            }
            // hh
#pragma unroll
            for (int mt = 0; mt < 4; ++mt)
#pragma unroll
                for (int nt = 0; nt < 4; ++nt)
                    mma16816(acc[mt][nt], af[mt], bh[nt]);
            // hl (A_hi x B_lo)
#pragma unroll
            for (int mt = 0; mt < 4; ++mt)
#pragma unroll
                for (int nt = 0; nt < 4; ++nt)
                    mma16816(acc[mt][nt], af[mt], bl[nt]);
            // lh: reload A_lo into af storage, reuse bh
#pragma unroll
            for (int mt = 0; mt < 4; ++mt) {
                int r0 = wm + mt * 16 + gid;
                af[mt][0] = *(const uint32_t*)&sAl[r0][kb];
                af[mt][1] = *(const uint32_t*)&sAl[r0 + 8][kb];
                af[mt][2] = *(const uint32_t*)&sAl[r0][kb + 8];
                af[mt][3] = *(const uint32_t*)&sAl[r0 + 8][kb + 8];
            }
#pragma unroll
            for (int mt = 0; mt < 4; ++mt)
#pragma unroll
                for (int nt = 0; nt < 4; ++nt)
                    mma16816(acc[mt][nt], af[mt], bh[nt]);
        }
        __syncthreads();
    }

    // epilogue
#pragma unroll
    for (int mt = 0; mt < 4; ++mt) {
        int r0 = bm + wm + mt * 16 + gid;
        int r1 = r0 + 8;
#pragma unroll
        for (int nt = 0; nt < 4; ++nt) {
            int col = bn + wn + nt * 8 + tig * 2;
            if (r0 < Me) {
                long off = (long)r0 * N + col;
                float2 v = make_float2(acc[mt][nt][0], acc[mt][nt][1]);
                if (Add) { v.x += Add[off]; v.y += Add[off + 1]; }
                *(float2*)(Cp + off) = v;
            }
            if (r1 < Me) {
                long off = (long)r1 * N + col;
                float2 v = make_float2(acc[mt][nt][2], acc[mt][nt][3]);
                if (Add) { v.x += Add[off]; v.y += Add[off + 1]; }
                *(float2*)(Cp + off) = v;
            }
        }
    }
}

// ---------------- causal GQA attention, fp32 flash-style; 64 q rows/block ----------------
__global__ __launch_bounds__(256)
void k_attn(const float* __restrict__ Q, const float* __restrict__ K,
            const float* __restrict__ V, float* __restrict__ O)
{
    extern __shared__ float smf[];
    float* Qs = smf;
    float* Ks = Qs + 64 * HD;
    float* Vs = Ks + 64 * HD;
    float* Ss = Vs + 64 * HD;

    int h   = blockIdx.y;
    int qb  = blockIdx.x * 64;
    int kvh = h >> 2;
    int tid = threadIdx.x;

    for (int f = tid; f < 64 * 32; f += 256) {
        int r = f >> 5, c = (f & 31) << 2;
        *(float4*)&Qs[r * HD + c] =
            *(const float4*)&Q[(long)(qb + r) * (NH*HD) + h * HD + c];
    }

    int r  = tid >> 2;
    int c0 = (tid & 3) * 32;
    int ty = tid >> 4, tx = tid & 15;

    float acc[32];
#pragma unroll
    for (int i = 0; i < 32; ++i) acc[i] = 0.f;
    float mx = -INFINITY, l = 0.f;
    const float scale = 0.0883883476483184f;

    int nkt = (qb >> 6) + 1;
    for (int kt = 0; kt < nkt; ++kt) {
        int kb = kt << 6;
        __syncthreads();
        for (int f = tid; f < 64 * 32; f += 256) {
            int rr = f >> 5, cc = (f & 31) << 2;
            *(float4*)&Ks[rr * HD + cc] =
                *(const float4*)&K[(long)(kb + rr) * (NKV*HD) + kvh * HD + cc];
            *(float4*)&Vs[rr * HD + cc] =
                *(const float4*)&V[(long)(kb + rr) * (NKV*HD) + kvh * HD + cc];
        }
        __syncthreads();

        float s4[4][4];
#pragma unroll
        for (int i = 0; i < 4; ++i)
#pragma unroll
            for (int j = 0; j < 4; ++j) s4[i][j] = 0.f;
        for (int d = 0; d < HD; d += 4) {
            float4 qv[4], kv[4];
#pragma unroll
            for (int i = 0; i < 4; ++i) qv[i] = *(const float4*)&Qs[(ty*4 + i) * HD + d];
#pragma unroll
            for (int j = 0; j < 4; ++j) kv[j] = *(const float4*)&Ks[(tx*4 + j) * HD + d];
#pragma unroll
            for (int i = 0; i < 4; ++i)
#pragma unroll
                for (int j = 0; j < 4; ++j) {
                    s4[i][j] = fmaf(qv[i].x, kv[j].x, s4[i][j]);
                    s4[i][j] = fmaf(qv[i].y, kv[j].y, s4[i][j]);
                    s4[i][j] = fmaf(qv[i].z, kv[j].z, s4[i][j]);
                    s4[i][j] = fmaf(qv[i].w, kv[j].w, s4[i][j]);
                }
        }
#pragma unroll
        for (int i = 0; i < 4; ++i)
#pragma unroll
            for (int j = 0; j < 4; ++j) {
                int qg = qb + ty*4 + i, kg = kb + tx*4 + j;
                Ss[(ty*4 + i) * 64 + tx*4 + j] = (kg <= qg) ? s4[i][j] * scale : -1e30f;
            }
        __syncthreads();

        int jc = (tid & 3) * 16;
        float tmax = -1e30f;
#pragma unroll
        for (int j = 0; j < 16; ++j) tmax = fmaxf(tmax, Ss[r * 64 + jc + j]);
        tmax = fmaxf(tmax, __shfl_xor_sync(0xffffffffu, tmax, 1));
        tmax = fmaxf(tmax, __shfl_xor_sync(0xffffffffu, tmax, 2));
        float mn = fmaxf(mx, tmax);
        float psum = 0.f;
#pragma unroll
        for (int j = 0; j < 16; ++j) {
            float p = expf(Ss[r * 64 + jc + j] - mn);
            Ss[r * 64 + jc + j] = p;
            psum += p;
        }
        psum += __shfl_xor_sync(0xffffffffu, psum, 1);
        psum += __shfl_xor_sync(0xffffffffu, psum, 2);
        float corr = expf(mx - mn);
        l = l * corr + psum;
        mx = mn;
#pragma unroll
        for (int i = 0; i < 32; ++i) acc[i] *= corr;
        __syncwarp();

        for (int j = 0; j < 64; ++j) {
            float p = Ss[r * 64 + j];
            const float4* v4 = (const float4*)&Vs[j * HD + c0];
#pragma unroll
            for (int i = 0; i < 8; ++i) {
                float4 vv = v4[i];
                acc[i*4+0] = fmaf(p, vv.x, acc[i*4+0]);
                acc[i*4+1] = fmaf(p, vv.y, acc[i*4+1]);
                acc[i*4+2] = fmaf(p, vv.z, acc[i*4+2]);
                acc[i*4+3] = fmaf(p, vv.w, acc[i*4+3]);
            }
        }
    }
    float inv = 1.f / l;
#pragma unroll
    for (int i = 0; i < 8; ++i) {
        float4 o4 = make_float4(acc[i*4]*inv, acc[i*4+1]*inv, acc[i*4+2]*inv, acc[i*4+3]*inv);
        *(float4*)&O[(long)(qb + r) * (NH*HD) + h * HD + c0 + i*4] = o4;
    }
}

// ---------------- elementwise silu(G)*U ----------------
__global__ void k_silu(const float* __restrict__ G, const float* __restrict__ U,
                       float* __restrict__ H, int n)
{
    int stride = gridDim.x * 256;
    for (int i = blockIdx.x * 256 + threadIdx.x; i < n; i += stride) {
        float g = G[i];
        H[i] = (g / (1.f + expf(-g))) * U[i];
    }
}

__global__ void k_silu_exp()
{
    int e = blockIdx.y;
    int n = g_cnt[e] * IR;
    int base = e * T * IR;
    int stride = gridDim.x * 256;
    for (int i = blockIdx.x * 256 + threadIdx.x; i < n; i += stride) {
        float g = g_eG[base + i];
        g_eH[base + i] = (g / (1.f + expf(-g))) * g_eU[base + i];
    }
}

// ---------------- router ----------------
__global__ void k_zero() { if (threadIdx.x < NEXP) g_cnt[threadIdx.x] = 0; }

__global__ void k_route(const float* __restrict__ x, const float* __restrict__ gw)
{
    int t = blockIdx.x;
    __shared__ float xs[DM];
    __shared__ float lg[NEXP];
    for (int d = threadIdx.x; d < DM; d += 256) xs[d] = x[(long)t * DM + d];
    __syncthreads();
    int e = threadIdx.x >> 4;
    int part = threadIdx.x & 15;
    float s = 0.f;
    const float* gr = gw + e * DM;
    for (int d = part; d < DM; d += 16) s = fmaf(xs[d], gr[d], s);
    s += __shfl_xor_sync(0xffffffffu, s, 1);
    s += __shfl_xor_sync(0xffffffffu, s, 2);
    s += __shfl_xor_sync(0xffffffffu, s, 4);
    s += __shfl_xor_sync(0xffffffffu, s, 8);
    if (part == 0) lg[e] = s;
    __syncthreads();
    if (threadIdx.x == 0) {
        float m = lg[0];
#pragma unroll
        for (int i = 1; i < NEXP; ++i) m = fmaxf(m, lg[i]);
        float p[NEXP]; float tot = 0.f;
#pragma unroll
        for (int i = 0; i < NEXP; ++i) { p[i] = expf(lg[i] - m); tot += p[i]; }
#pragma unroll
        for (int i = 0; i < NEXP; ++i) p[i] /= tot;
        bool used[NEXP];
#pragma unroll
        for (int i = 0; i < NEXP; ++i) used[i] = false;
        int sel[TK]; float sw[TK]; float wsum = 0.f;
        for (int j = 0; j < TK; ++j) {
            int b = 0; float bv = -1.f;
#pragma unroll
            for (int i = 0; i < NEXP; ++i)
                if (!used[i] && p[i] > bv) { bv = p[i]; b = i; }
            used[b] = true; sel[j] = b; sw[j] = bv; wsum += bv;
        }
        for (int j = 0; j < TK; ++j) {
            int ee = sel[j];
            int slot = atomicAdd(&g_cnt[ee], 1);
            g_tok[ee * T + slot] = t;
            g_eid[t * TK + j]  = ee;
            g_slot[t * TK + j] = slot;
            g_wt[t * TK + j]   = sw[j] / wsum;
        }
    }
}

// ---------------- final combine ----------------
__global__ void k_combine(const float* __restrict__ hid, const float* __restrict__ sh,
                          float* __restrict__ out)
{
    int t = blockIdx.x;
    long bo[TK]; float w[TK];
#pragma unroll
    for (int j = 0; j < TK; ++j) {
        int e = g_eid[t * TK + j];
        int s = g_slot[t * TK + j];
        w[j] = g_wt[t * TK + j];
        bo[j] = ((long)e * T + s) * (long)DM;
    }
    for (int d = threadIdx.x; d < DM; d += 256) {
        float v = hid[(long)t * DM + d] + sh[(long)t * DM + d];
#pragma unroll
        for (int j = 0; j < TK; ++j) v = fmaf(w[j], g_eO[bo[j] + d], v);
        out[(long)t * DM + d] = v;
    }
}

// ---------------- host ----------------
extern "C" void kernel_launch(void* const* d_in, const int* in_sizes, int n_in,
                              void* d_out, int out_size)
{
    (void)in_sizes; (void)n_in; (void)out_size;
    const float* hs   = (const float*)d_in[0];
    const float* cosT = (const float*)d_in[2];
    const float* sinT = (const float*)d_in[3];
    const float* ln1  = (const float*)d_in[4];
    const float* ln2  = (const float*)d_in[5];
    const float* wq   = (const float*)d_in[6];
    const float* wk   = (const float*)d_in[7];
    const float* wv   = (const float*)d_in[8];
    const float* wo   = (const float*)d_in[9];
    const float* qn   = (const float*)d_in[10];
    const float* kn   = (const float*)d_in[11];
    const float* gw   = (const float*)d_in[12];
    const float* sg   = (const float*)d_in[13];
    const float* su   = (const float*)d_in[14];
    const float* sd   = (const float*)d_in[15];
    const float* eg   = (const float*)d_in[16];
    const float* eu   = (const float*)d_in[17];
    const float* ed   = (const float*)d_in[18];
    float* out = (float*)d_out;

    float *p_xn, *p_q, *p_k, *p_v, *p_attn, *p_hid, *p_x2n;
    float *p_G, *p_U, *p_H, *p_sh, *p_eG, *p_eU, *p_eH, *p_eO;
    int *p_cnt, *p_tok;
    cudaGetSymbolAddress((void**)&p_xn,   g_xn);
    cudaGetSymbolAddress((void**)&p_q,    g_q);
    cudaGetSymbolAddress((void**)&p_k,    g_k);
    cudaGetSymbolAddress((void**)&p_v,    g_v);
    cudaGetSymbolAddress((void**)&p_attn, g_attn);
    cudaGetSymbolAddress((void**)&p_hid,  g_hid);
    cudaGetSymbolAddress((void**)&p_x2n,  g_x2n);
    cudaGetSymbolAddress((void**)&p_G,    g_G);
    cudaGetSymbolAddress((void**)&p_U,    g_U);
    cudaGetSymbolAddress((void**)&p_H,    g_H);
    cudaGetSymbolAddress((void**)&p_sh,   g_sh);
    cudaGetSymbolAddress((void**)&p_eG,   g_eG);
    cudaGetSymbolAddress((void**)&p_eU,   g_eU);
    cudaGetSymbolAddress((void**)&p_eH,   g_eH);
    cudaGetSymbolAddress((void**)&p_eO,   g_eO);
    cudaGetSymbolAddress((void**)&p_cnt,  g_cnt);
    cudaGetSymbolAddress((void**)&p_tok,  g_tok);

    cudaFuncSetAttribute(k_attn, cudaFuncAttributeMaxDynamicSharedMemorySize, 114688);

    // 1) pre-attention RMSNorm
    k_rms<<<T, 256>>>(hs, ln1, p_xn);

    // 2) QKV projections (HMMA tensor cores)
    k_gemm_mma<<<dim3(16, 16, 1), 256>>>(p_xn, 0, wq, 0, p_q, 0, nullptr,
                                         T, NH*HD, DM, nullptr, nullptr, nullptr);
    k_gemm_mma<<<dim3(4, 16, 1), 256>>>(p_xn, 0, wk, 0, p_k, 0, nullptr,
                                        T, NKV*HD, DM, nullptr, nullptr, nullptr);
    k_gemm_mma<<<dim3(4, 16, 1), 256>>>(p_xn, 0, wv, 0, p_v, 0, nullptr,
                                        T, NKV*HD, DM, nullptr, nullptr, nullptr);

    // 3) RoPE + QK-RMSNorm
    k_rope<<<dim3(T, NH + NKV), 128>>>(p_q, p_k, cosT, sinT, qn, kn);

    // 4) causal GQA attention (fp32 — next optimization target)
    k_attn<<<dim3(T / 64, NH), 256, 114688>>>(p_q, p_k, p_v, p_attn);

    // 5) output projection + residual
    k_gemm_mma<<<dim3(16, 16, 1), 256>>>(p_attn, 0, wo, 0, p_hid, 0, hs,
                                         T, DM, NH*HD, nullptr, nullptr, nullptr);

    // 6) post-attention RMSNorm
    k_rms<<<T, 256>>>(p_hid, ln2, p_x2n);

    // 7) shared-expert MLP
    k_gemm_mma<<<dim3(32, 16, 1), 256>>>(p_x2n, 0, sg, 0, p_G, 0, nullptr,
                                         T, ISH, DM, nullptr, nullptr, nullptr);
    k_gemm_mma<<<dim3(32, 16, 1), 256>>>(p_x2n, 0, su, 0, p_U, 0, nullptr,
                                         T, ISH, DM, nullptr, nullptr, nullptr);
    k_silu<<<4096, 256>>>(p_G, p_U, p_H, T * ISH);
    k_gemm_mma<<<dim3(16, 16, 1), 256>>>(p_H, 0, sd, 0, p_sh, 0, nullptr,
                                         T, DM, ISH, nullptr, nullptr, nullptr);

    // 8) routing
    k_zero<<<1, 32>>>();
    k_route<<<T, 256>>>(p_x2n, gw);

    // 9) routed experts
    k_gemm_mma<<<dim3(8, 16, NEXP), 256>>>(nullptr, 0, eg, (long)IR * DM,
                                           p_eG, (long)T * IR, nullptr,
                                           0, IR, DM, p_cnt, p_tok, p_x2n);
    k_gemm_mma<<<dim3(8, 16, NEXP), 256>>>(nullptr, 0, eu, (long)IR * DM,
                                           p_eU, (long)T * IR, nullptr,
                                           0, IR, DM, p_cnt, p_tok, p_x2n);
    k_silu_exp<<<dim3(128, NEXP), 256>>>();
    k_gemm_mma<<<dim3(16, 16, NEXP), 256>>>(p_eH, (long)T * IR, ed, (long)DM * IR,
                                            p_eO, (long)T * DM, nullptr,
                                            0, DM, IR, p_cnt, nullptr, nullptr);

    // 10) combine
    k_combine<<<T, 256>>>(p_hid, p_sh, out);
}